// round 5
// baseline (speedup 1.0000x reference)
#include <cuda_runtime.h>
#include <cuda_bf16.h>
#include <cuda_fp8.h>
#include <cstdint>
#include <math_constants.h>

// ---------------------------------------------------------------------------
// Problem constants
// ---------------------------------------------------------------------------
#define NROWS  32768        // 8 * 4096 query rows
#define KCODES 8192
#define DIM    256          // GEMM-K
#define MT     128          // rows per CTA
#define NTILE  256          // codes per N-tile
#define KTILES (KCODES / NTILE)       // 32
#define NSTG   (KTILES * 8)           // 256 k32-stages total

// SMEM layout (bytes)
#define ROWA        272     // 256 fp8 + 16 pad (conflict-free ldmatrix)
#define A_LO_OFF    34816   // 128*272
#define SM_B        69632   // ring of 4 stages
#define STAGE_BYTES 24576   // hi block 12288 + lo block 12288
#define LO_OFF      12288
#define ROWB        48      // 32B k32-slice + 16 pad
#define SM_CSQ      167936  // 2 x 1KB double-buffered csq
#define SMEM_TOTAL  169984

// ---------------------------------------------------------------------------
// Device scratch (no allocations allowed)
// ---------------------------------------------------------------------------
__device__ uint32_t g_cb_hi[KCODES * 64];   // e4m3 hi, 256B per code row
__device__ uint32_t g_cb_lo[KCODES * 64];   // e4m3 lo residual
__device__ __align__(16) float g_csq[KCODES];
__device__ int g_cand[NROWS * 8];

// ---------------------------------------------------------------------------
// PTX helpers (base ISA only: ldmatrix / mma.sync / cp.async)
// ---------------------------------------------------------------------------
__device__ __forceinline__ uint32_t smem_to_u32(const void* smem_ptr) {
    uint32_t addr;
    asm("{ .reg .u64 tmp; cvta.to.shared.u64 tmp, %1; cvt.u32.u64 %0, tmp; }"
        : "=r"(addr) : "l"(smem_ptr));
    return addr;
}

#define CP_ASYNC16(dst, src) \
    asm volatile("cp.async.cg.shared.global [%0], [%1], 16;" \
        :: "r"((uint32_t)(dst)), "l"((const void*)(src)) : "memory")
#define CP_COMMIT() asm volatile("cp.async.commit_group;" ::: "memory")
#define CP_WAIT(n)  asm volatile("cp.async.wait_group %0;" :: "n"(n) : "memory")

#define LDSM_X4(r, addr) \
    asm volatile("ldmatrix.sync.aligned.m8n8.x4.shared.b16 {%0,%1,%2,%3}, [%4];" \
        : "=r"((r)[0]), "=r"((r)[1]), "=r"((r)[2]), "=r"((r)[3]) : "r"(addr))

// fp8 e4m3 MMA: m16n8k32, fp32 accumulate (base PTX, sm_89+)
#define MMA_FP8(c, a, b) \
    asm volatile("mma.sync.aligned.m16n8k32.row.col.f32.e4m3.e4m3.f32 " \
        "{%0,%1,%2,%3}, {%4,%5,%6,%7}, {%8,%9}, {%0,%1,%2,%3};" \
        : "+f"((c)[0]), "+f"((c)[1]), "+f"((c)[2]), "+f"((c)[3]) \
        : "r"((a)[0]), "r"((a)[1]), "r"((a)[2]), "r"((a)[3]), \
          "r"((b)[0]), "r"((b)[1]))

// merge candidate (C1,J1) then (C2,J2) into running top-2 (B1,I1,B2,I2)
#define MERGE2(B1, I1, B2, I2, C1, J1, C2, J2) do { \
    if ((C1) < (B1)) { \
        float _nb2; int _ni2; \
        if ((B1) < (C2)) { _nb2 = (B1); _ni2 = (I1); } \
        else             { _nb2 = (C2); _ni2 = (J2); } \
        (B1) = (C1); (I1) = (J1); (B2) = _nb2; (I2) = _ni2; \
    } else if ((C1) < (B2)) { (B2) = (C1); (I2) = (J1); } \
} while (0)

// ---------------------------------------------------------------------------
// e4m3 hi/lo split of one float
// ---------------------------------------------------------------------------
__device__ __forceinline__ void split_fp8(float v, uint32_t& h, uint32_t& l) {
    __nv_fp8_storage_t hs = __nv_cvt_float_to_fp8(v, __NV_SATFINITE, __NV_E4M3);
    float hv = __half2float(__nv_cvt_fp8_to_halfraw(hs, __NV_E4M3));
    __nv_fp8_storage_t ls = __nv_cvt_float_to_fp8(v - hv, __NV_SATFINITE, __NV_E4M3);
    h = (uint32_t)hs;
    l = (uint32_t)ls;
}

// pack 4 floats -> 4 hi e4m3 bytes + 4 lo e4m3 bytes
__device__ __forceinline__ void split4(float4 v, uint32_t& hu, uint32_t& lu) {
    uint32_t h0, l0, h1, l1, h2, l2, h3, l3;
    split_fp8(v.x, h0, l0); split_fp8(v.y, h1, l1);
    split_fp8(v.z, h2, l2); split_fp8(v.w, h3, l3);
    hu = h0 | (h1 << 8) | (h2 << 16) | (h3 << 24);
    lu = l0 | (l1 << 8) | (l2 << 16) | (l3 << 24);
}

// ---------------------------------------------------------------------------
// Codebook prep: one warp per code row -> e4m3 hi/lo packed + fp32 csq.
// ---------------------------------------------------------------------------
__global__ __launch_bounds__(256) void vq_prep(const float* __restrict__ cb) {
    int row  = blockIdx.x * 8 + (threadIdx.x >> 5);
    int lane = threadIdx.x & 31;
    const float4* cr = (const float4*)(cb + (size_t)row * DIM);
    float sq = 0.f;
#pragma unroll
    for (int q = 0; q < 2; q++) {
        float4 v = cr[lane * 2 + q];
        sq += v.x * v.x + v.y * v.y + v.z * v.z + v.w * v.w;
        uint32_t hu, lu;
        split4(v, hu, lu);
        g_cb_hi[row * 64 + lane * 2 + q] = hu;
        g_cb_lo[row * 64 + lane * 2 + q] = lu;
    }
#pragma unroll
    for (int off = 16; off; off >>= 1) sq += __shfl_xor_sync(0xffffffffu, sq, off);
    if (lane == 0) g_csq[row] = sq;
}

// ---------------------------------------------------------------------------
// Prefetch one k32 stage (256 codes x 32B hi + 32B lo) into the ring.
// ---------------------------------------------------------------------------
__device__ __forceinline__ void prefetch_stage(uint32_t sbase, int gs, int tid) {
    int ktile = gs >> 3, s = gs & 7;
    size_t srcoff = ((size_t)(ktile * NTILE + tid)) * 256 + s * 32;
    const char* hs = (const char*)g_cb_hi + srcoff;
    const char* ls = (const char*)g_cb_lo + srcoff;
    uint32_t dst = sbase + SM_B + (uint32_t)(gs & 3) * STAGE_BYTES + tid * ROWB;
    CP_ASYNC16(dst, hs);
    CP_ASYNC16(dst + 16, hs + 16);
    CP_ASYNC16(dst + LO_OFF, ls);
    CP_ASYNC16(dst + LO_OFF + 16, ls + 16);
}

// ---------------------------------------------------------------------------
// Main kernel: 128 rows/CTA, fp8 3-pass (ah*bh + ah*bl + al*bh), 64x64 warp
// tiles, 4-deep cp.async ring, per-row top-2 per warp-column -> 8 candidates.
// ---------------------------------------------------------------------------
__global__ __launch_bounds__(256, 1) void vq_main(const float* __restrict__ x) {
    extern __shared__ char smem[];
    const uint32_t sbase = smem_to_u32(smem);
    const int tid  = threadIdx.x;
    const int wid  = tid >> 5;
    const int lane = tid & 31;
    const int wm = wid >> 2;                // 0..1 : 64-row band
    const int wn = wid & 3;                 // 0..3 : 64-col band
    const int rowBase = blockIdx.x * MT;

    // ---- A split into smem hi/lo e4m3 (row stride 272B) ----
    {
        int r = tid >> 1, h = tid & 1;
        const float4* xr = (const float4*)(x + (size_t)(rowBase + r) * DIM + h * 128);
        uint32_t* ah = (uint32_t*)(smem + r * ROWA + h * 128);
        uint32_t* al = (uint32_t*)(smem + A_LO_OFF + r * ROWA + h * 128);
#pragma unroll
        for (int q = 0; q < 32; q++) {
            uint32_t hu, lu;
            split4(xr[q], hu, lu);
            ah[q] = hu;
            al[q] = lu;
        }
    }

    // ---- prologue prefetch: stages 0..2 + csq tile 0 ----
    prefetch_stage(sbase, 0, tid);
    if (tid < 64) CP_ASYNC16(sbase + SM_CSQ + tid * 16, (const char*)g_csq + tid * 16);
    CP_COMMIT();
    prefetch_stage(sbase, 1, tid); CP_COMMIT();
    prefetch_stage(sbase, 2, tid); CP_COMMIT();

    // per-lane ldmatrix base addresses (16B-granule b16 tiles; fp8 pairs = b16)
    const uint32_t aHiB = sbase + (uint32_t)((wm * 64 + (lane & 15)) * ROWA
                                             + ((lane >> 4) & 1) * 16);
    const uint32_t aLoB = aHiB + A_LO_OFF;
    const uint32_t bOff = (uint32_t)((wn * 64 + ((lane >> 4) & 1) * 8 + (lane & 7)) * ROWB
                                     + ((lane >> 3) & 1) * 16);

    float c[4][8][4];
#pragma unroll
    for (int a = 0; a < 4; a++)
#pragma unroll
        for (int b = 0; b < 8; b++)
#pragma unroll
            for (int v = 0; v < 4; v++) c[a][b][v] = 0.f;

    float b1r[8], b2r[8];
    int   i1r[8], i2r[8];
#pragma unroll
    for (int s = 0; s < 8; s++) {
        b1r[s] = CUDART_INF_F; b2r[s] = CUDART_INF_F; i1r[s] = 0; i2r[s] = 1;
    }

    for (int gs = 0; gs < NSTG; gs++) {
        CP_WAIT(2);
        __syncthreads();
        if (gs + 3 < NSTG) {
            prefetch_stage(sbase, gs + 3, tid);
            if ((((gs + 3) & 7) == 0) && tid < 64) {
                int nk = (gs + 3) >> 3;
                CP_ASYNC16(sbase + SM_CSQ + (nk & 1) * 1024 + tid * 16,
                           (const char*)g_csq + (size_t)nk * 1024 + tid * 16);
            }
        }
        CP_COMMIT();

        const int s = gs & 7;
        const uint32_t sb = sbase + SM_B + (uint32_t)(gs & 3) * STAGE_BYTES;

        // B hi fragments (4 regs cover two n8 frags each)
        uint32_t bh[4][4];
#pragma unroll
        for (int np = 0; np < 4; np++) LDSM_X4(bh[np], sb + bOff + np * (16 * ROWB));
        // A hi fragments
        uint32_t ah[4][4];
#pragma unroll
        for (int mt = 0; mt < 4; mt++) LDSM_X4(ah[mt], aHiB + mt * (16 * ROWA) + s * 32);
        // pass 1: ah * bh
#pragma unroll
        for (int mt = 0; mt < 4; mt++)
#pragma unroll
            for (int np = 0; np < 4; np++) {
                MMA_FP8(c[mt][2 * np + 0], ah[mt], bh[np]);
                MMA_FP8(c[mt][2 * np + 1], ah[mt], bh[np] + 2);
            }
        // pass 2: ah * bl
        uint32_t bl[4][4];
#pragma unroll
        for (int np = 0; np < 4; np++)
            LDSM_X4(bl[np], sb + LO_OFF + bOff + np * (16 * ROWB));
#pragma unroll
        for (int mt = 0; mt < 4; mt++)
#pragma unroll
            for (int np = 0; np < 4; np++) {
                MMA_FP8(c[mt][2 * np + 0], ah[mt], bl[np]);
                MMA_FP8(c[mt][2 * np + 1], ah[mt], bl[np] + 2);
            }
        // pass 3: al * bh
        uint32_t al[4][4];
#pragma unroll
        for (int mt = 0; mt < 4; mt++) LDSM_X4(al[mt], aLoB + mt * (16 * ROWA) + s * 32);
#pragma unroll
        for (int mt = 0; mt < 4; mt++)
#pragma unroll
            for (int np = 0; np < 4; np++) {
                MMA_FP8(c[mt][2 * np + 0], al[mt], bh[np]);
                MMA_FP8(c[mt][2 * np + 1], al[mt], bh[np] + 2);
            }

        if (s == 7) {
            const int ktile = gs >> 3;
            const float* csq_s = (const float*)(smem + SM_CSQ + (ktile & 1) * 1024) + wn * 64;
            float csqr[16];
#pragma unroll
            for (int nt = 0; nt < 8; nt++) {
                csqr[nt * 2 + 0] = csq_s[nt * 8 + (lane & 3) * 2 + 0];
                csqr[nt * 2 + 1] = csq_s[nt * 8 + (lane & 3) * 2 + 1];
            }
            const int kb = ktile * NTILE + wn * 64 + (lane & 3) * 2;
#pragma unroll
            for (int slot = 0; slot < 8; slot++) {
                const int mt = slot >> 1, h = slot & 1;
                float m = CUDART_INF_F;
#pragma unroll
                for (int nt = 0; nt < 8; nt++) {
                    m = fminf(m, fmaf(-2.f, c[mt][nt][h * 2 + 0], csqr[nt * 2 + 0]));
                    m = fminf(m, fmaf(-2.f, c[mt][nt][h * 2 + 1], csqr[nt * 2 + 1]));
                }
                if (m < b2r[slot]) {
#pragma unroll
                    for (int nt = 0; nt < 8; nt++)
#pragma unroll
                        for (int u = 0; u < 2; u++) {
                            float sc = fmaf(-2.f, c[mt][nt][h * 2 + u], csqr[nt * 2 + u]);
                            int k = kb + nt * 8 + u;
                            if (sc < b1r[slot]) {
                                b2r[slot] = b1r[slot]; i2r[slot] = i1r[slot];
                                b1r[slot] = sc;        i1r[slot] = k;
                            } else if (sc < b2r[slot]) {
                                b2r[slot] = sc; i2r[slot] = k;
                            }
                        }
                }
            }
#pragma unroll
            for (int a = 0; a < 4; a++)
#pragma unroll
                for (int b = 0; b < 8; b++)
#pragma unroll
                    for (int v = 0; v < 4; v++) c[a][b][v] = 0.f;
        }
    }

    // ---- lane-quad merge (lanes sharing a row differ in lane&3) ----
#pragma unroll
    for (int slot = 0; slot < 8; slot++) {
        float B1 = b1r[slot], B2 = b2r[slot];
        int   I1 = i1r[slot], I2 = i2r[slot];
#pragma unroll
        for (int off = 1; off <= 2; off <<= 1) {
            float C1 = __shfl_xor_sync(0xffffffffu, B1, off);
            int   J1 = __shfl_xor_sync(0xffffffffu, I1, off);
            float C2 = __shfl_xor_sync(0xffffffffu, B2, off);
            int   J2 = __shfl_xor_sync(0xffffffffu, I2, off);
            MERGE2(B1, I1, B2, I2, C1, J1, C2, J2);
        }
        b1r[slot] = B1; i1r[slot] = I1; b2r[slot] = B2; i2r[slot] = I2;
    }

    __syncthreads();
    int* mi1 = (int*)(smem + SM_B);
    int* mi2 = (int*)(smem + SM_B + 2048);
    if ((lane & 3) == 0) {
#pragma unroll
        for (int slot = 0; slot < 8; slot++) {
            int row = wm * 64 + (slot >> 1) * 16 + (slot & 1) * 8 + (lane >> 2);
            int idx = wn * 128 + row;
            mi1[idx] = i1r[slot]; mi2[idx] = i2r[slot];
        }
    }
    __syncthreads();
    if (tid < 128) {
#pragma unroll
        for (int w = 0; w < 4; w++) {
            g_cand[(rowBase + tid) * 8 + w * 2 + 0] = mi1[w * 128 + tid];
            g_cand[(rowBase + tid) * 8 + w * 2 + 1] = mi2[w * 128 + tid];
        }
    }
}

// ---------------------------------------------------------------------------
// Exact fp32 rescore of 8 candidates + gather. One warp per row.
// ---------------------------------------------------------------------------
__global__ __launch_bounds__(256) void vq_rescore(const float* __restrict__ x,
                                                  const float* __restrict__ cb,
                                                  float* __restrict__ out) {
    int row  = blockIdx.x * 8 + (threadIdx.x >> 5);
    int lane = threadIdx.x & 31;
    int kc[8];
#pragma unroll
    for (int c = 0; c < 8; c++) kc[c] = g_cand[row * 8 + c];
    const float4* xr = (const float4*)(x + (size_t)row * DIM);
    float4 xv0 = xr[lane], xv1 = xr[lane + 32];
    float d[8];
#pragma unroll
    for (int c = 0; c < 8; c++) {
        const float4* cc = (const float4*)(cb + (size_t)kc[c] * DIM);
        float4 a = cc[lane], b = cc[lane + 32];
        d[c] = xv0.x * a.x + xv0.y * a.y + xv0.z * a.z + xv0.w * a.w
             + xv1.x * b.x + xv1.y * b.y + xv1.z * b.z + xv1.w * b.w;
    }
#pragma unroll
    for (int off = 16; off; off >>= 1)
#pragma unroll
        for (int c = 0; c < 8; c++) d[c] += __shfl_xor_sync(0xffffffffu, d[c], off);
    float best = CUDART_INF_F; int bi = 0x7fffffff;
#pragma unroll
    for (int c = 0; c < 8; c++) {
        float s = fmaf(-2.f, d[c], g_csq[kc[c]]);
        if (s < best || (s == best && kc[c] < bi)) { best = s; bi = kc[c]; }
    }
    if (lane == 0) out[row] = (float)bi;
    const float4* cw = (const float4*)(cb + (size_t)bi * DIM);
    float4* oq = (float4*)(out + NROWS + (size_t)row * DIM);
    oq[lane] = cw[lane];
    oq[lane + 32] = cw[lane + 32];
}

// ---------------------------------------------------------------------------
extern "C" void kernel_launch(void* const* d_in, const int* in_sizes, int n_in,
                              void* d_out, int out_size) {
    const float* x  = (const float*)d_in[0];   // [8, 4096, 256] f32
    const float* cb = (const float*)d_in[1];   // [8192, 256] f32
    float* out = (float*)d_out;

    cudaFuncSetAttribute(vq_main, cudaFuncAttributeMaxDynamicSharedMemorySize,
                         SMEM_TOTAL);

    vq_prep<<<KCODES / 8, 256>>>(cb);
    vq_main<<<NROWS / MT, 256, SMEM_TOTAL>>>(x);
    vq_rescore<<<NROWS / 8, 256>>>(x, cb, out);
}

// round 6
// speedup vs baseline: 1.9784x; 1.9784x over previous
#include <cuda_runtime.h>
#include <cuda_bf16.h>
#include <cstdint>
#include <math_constants.h>

// ---------------------------------------------------------------------------
// Problem constants
// ---------------------------------------------------------------------------
#define NROWS  32768        // 8 * 4096 query rows
#define KCODES 8192
#define DIM    256          // GEMM-K
#define MT     128          // rows per CTA
#define NTILE  256          // codes per N-tile
#define CHUNK  2048         // codes per CTA (4 chunks cover KCODES)
#define KT_PER_CHUNK (CHUNK / NTILE)   // 8
#define NSTG   (KT_PER_CHUNK * 16)     // 128 k16-stages per CTA

// SMEM layout (bytes)
#define ROWA        528     // 256 bf16 + 8 pad (conflict-free ldmatrix)
#define SM_B        67584   // ring of 4 stages after A (128*528)
#define STAGE_BYTES 12288   // 256 codes * 48B
#define ROWB        48      // 32B k-slice + 16 pad
#define SM_CSQ      116736  // 2 x 1KB double-buffered csq
#define SMEM_TOTAL  118784

// ---------------------------------------------------------------------------
// Device scratch (no allocations allowed)
// ---------------------------------------------------------------------------
__device__ uint4 g_cb_hi4[KCODES * DIM / 8];   // bf16 hi, 512B per code row
__device__ __align__(16) float g_csq[KCODES];
__device__ int g_cand[NROWS * 8];              // 2 per chunk x 4 chunks

// ---------------------------------------------------------------------------
// PTX helpers (base ISA only: ldmatrix / mma.sync / cp.async)
// ---------------------------------------------------------------------------
__device__ __forceinline__ uint32_t smem_to_u32(const void* smem_ptr) {
    uint32_t addr;
    asm("{ .reg .u64 tmp; cvta.to.shared.u64 tmp, %1; cvt.u32.u64 %0, tmp; }"
        : "=r"(addr) : "l"(smem_ptr));
    return addr;
}

#define CP_ASYNC16(dst, src) \
    asm volatile("cp.async.cg.shared.global [%0], [%1], 16;" \
        :: "r"((uint32_t)(dst)), "l"((const void*)(src)) : "memory")
#define CP_COMMIT() asm volatile("cp.async.commit_group;" ::: "memory")
#define CP_WAIT(n)  asm volatile("cp.async.wait_group %0;" :: "n"(n) : "memory")

#define LDSM_X4(r, addr) \
    asm volatile("ldmatrix.sync.aligned.m8n8.x4.shared.b16 {%0,%1,%2,%3}, [%4];" \
        : "=r"((r)[0]), "=r"((r)[1]), "=r"((r)[2]), "=r"((r)[3]) : "r"(addr))

#define MMA_BF16(c, a, b) \
    asm volatile("mma.sync.aligned.m16n8k16.row.col.f32.bf16.bf16.f32 " \
        "{%0,%1,%2,%3}, {%4,%5,%6,%7}, {%8,%9}, {%0,%1,%2,%3};" \
        : "+f"((c)[0]), "+f"((c)[1]), "+f"((c)[2]), "+f"((c)[3]) \
        : "r"((a)[0]), "r"((a)[1]), "r"((a)[2]), "r"((a)[3]), \
          "r"((b)[0]), "r"((b)[1]))

// merge candidate (C1,J1) then (C2,J2) into running top-2 (B1,I1,B2,I2)
#define MERGE2(B1, I1, B2, I2, C1, J1, C2, J2) do { \
    if ((C1) < (B1)) { \
        float _nb2; int _ni2; \
        if ((B1) < (C2)) { _nb2 = (B1); _ni2 = (I1); } \
        else             { _nb2 = (C2); _ni2 = (J2); } \
        (B1) = (C1); (I1) = (J1); (B2) = _nb2; (I2) = _ni2; \
    } else if ((C1) < (B2)) { (B2) = (C1); (I2) = (J1); } \
} while (0)

// ---------------------------------------------------------------------------
// Codebook prep: one warp per code row. bf16 hi + fp32 csq.
// ---------------------------------------------------------------------------
__global__ __launch_bounds__(256) void vq_prep(const float* __restrict__ cb) {
    int row  = blockIdx.x * 8 + (threadIdx.x >> 5);
    int lane = threadIdx.x & 31;
    const float4* cr = (const float4*)(cb + (size_t)row * DIM);
    float sq = 0.f;
    uint32_t hw[4];
#pragma unroll
    for (int q = 0; q < 2; q++) {
        float4 v = cr[lane * 2 + q];
        sq += v.x * v.x + v.y * v.y + v.z * v.z + v.w * v.w;
        __nv_bfloat162 p0; p0.x = __float2bfloat16_rn(v.x); p0.y = __float2bfloat16_rn(v.y);
        __nv_bfloat162 p1; p1.x = __float2bfloat16_rn(v.z); p1.y = __float2bfloat16_rn(v.w);
        hw[q * 2 + 0] = *reinterpret_cast<uint32_t*>(&p0);
        hw[q * 2 + 1] = *reinterpret_cast<uint32_t*>(&p1);
    }
    g_cb_hi4[row * 32 + lane] = make_uint4(hw[0], hw[1], hw[2], hw[3]);
#pragma unroll
    for (int off = 16; off; off >>= 1) sq += __shfl_xor_sync(0xffffffffu, sq, off);
    if (lane == 0) g_csq[row] = sq;
}

// ---------------------------------------------------------------------------
// Prefetch one k16 stage (256 codes x 32B) into the ring.
// ---------------------------------------------------------------------------
__device__ __forceinline__ void prefetch_stage(uint32_t sbase, int chunkBase,
                                               int gs, int tid) {
    int ktile = gs >> 4, s = gs & 15;
    const char* src = (const char*)g_cb_hi4
        + ((size_t)(chunkBase + ktile * NTILE + tid)) * 512 + s * 32;
    uint32_t dst = sbase + SM_B + (uint32_t)(gs & 3) * STAGE_BYTES + tid * ROWB;
    CP_ASYNC16(dst, src);
    CP_ASYNC16(dst + 16, src + 16);
}

// ---------------------------------------------------------------------------
// Main kernel: grid 1024. CTA = (row block 128) x (code chunk 2048).
// 1-pass bf16 (A hi x B hi), 64x64 warp tiles, 4-deep cp.async ring,
// per-row chunk top-2 -> g_cand[row][chunk*2 .. chunk*2+1].
// ---------------------------------------------------------------------------
__global__ __launch_bounds__(256, 1) void vq_main(const float* __restrict__ x) {
    extern __shared__ char smem[];
    const uint32_t sbase = smem_to_u32(smem);
    const int tid  = threadIdx.x;
    const int wid  = tid >> 5;
    const int lane = tid & 31;
    const int wm = wid >> 2;                // 0..1 : 64-row band
    const int wn = wid & 3;                 // 0..3 : 64-col band
    const int rowBase   = (blockIdx.x >> 2) * MT;
    const int chunk     = blockIdx.x & 3;
    const int chunkBase = chunk * CHUNK;

    // ---- A -> bf16 in smem (row stride 528B) ----
    {
        int r = tid >> 1, h = tid & 1;
        const float4* xr = (const float4*)(x + (size_t)(rowBase + r) * DIM + h * 128);
        uint32_t* ah = (uint32_t*)(smem + r * ROWA + h * 256);
#pragma unroll
        for (int q = 0; q < 32; q++) {
            float4 v = xr[q];
            __nv_bfloat162 p0; p0.x = __float2bfloat16_rn(v.x); p0.y = __float2bfloat16_rn(v.y);
            __nv_bfloat162 p1; p1.x = __float2bfloat16_rn(v.z); p1.y = __float2bfloat16_rn(v.w);
            ah[q * 2 + 0] = *reinterpret_cast<uint32_t*>(&p0);
            ah[q * 2 + 1] = *reinterpret_cast<uint32_t*>(&p1);
        }
    }

    // ---- prologue prefetch: stages 0..2 + csq tile 0 ----
    prefetch_stage(sbase, chunkBase, 0, tid);
    if (tid < 64) CP_ASYNC16(sbase + SM_CSQ + tid * 16,
                             (const char*)(g_csq + chunkBase) + tid * 16);
    CP_COMMIT();
    prefetch_stage(sbase, chunkBase, 1, tid); CP_COMMIT();
    prefetch_stage(sbase, chunkBase, 2, tid); CP_COMMIT();

    // per-lane ldmatrix base addresses
    const uint32_t aHiB = sbase + (uint32_t)((wm * 64 + (lane & 15)) * ROWA
                                             + ((lane >> 4) & 1) * 16);
    const uint32_t bOff = (uint32_t)((wn * 64 + ((lane >> 4) & 1) * 8 + (lane & 7)) * ROWB
                                     + ((lane >> 3) & 1) * 16);

    float c[4][8][4];
#pragma unroll
    for (int a = 0; a < 4; a++)
#pragma unroll
        for (int b = 0; b < 8; b++)
#pragma unroll
            for (int v = 0; v < 4; v++) c[a][b][v] = 0.f;

    float b1r[8], b2r[8];
    int   i1r[8], i2r[8];
#pragma unroll
    for (int s = 0; s < 8; s++) {
        b1r[s] = CUDART_INF_F; b2r[s] = CUDART_INF_F; i1r[s] = 0; i2r[s] = 1;
    }

    for (int gs = 0; gs < NSTG; gs++) {
        CP_WAIT(2);
        __syncthreads();
        if (gs + 3 < NSTG) {
            prefetch_stage(sbase, chunkBase, gs + 3, tid);
            if ((((gs + 3) & 15) == 0) && tid < 64) {
                int nk = (gs + 3) >> 4;
                CP_ASYNC16(sbase + SM_CSQ + (nk & 1) * 1024 + tid * 16,
                           (const char*)(g_csq + chunkBase + nk * NTILE) + tid * 16);
            }
        }
        CP_COMMIT();

        const int s = gs & 15;
        const uint32_t sb = sbase + SM_B + (uint32_t)(gs & 3) * STAGE_BYTES;

        uint32_t bf[4][4];
#pragma unroll
        for (int np = 0; np < 4; np++) LDSM_X4(bf[np], sb + bOff + np * (16 * ROWB));
        uint32_t ah[4][4];
#pragma unroll
        for (int mt = 0; mt < 4; mt++) LDSM_X4(ah[mt], aHiB + mt * (16 * ROWA) + s * 32);
#pragma unroll
        for (int mt = 0; mt < 4; mt++)
#pragma unroll
            for (int np = 0; np < 4; np++) {
                MMA_BF16(c[mt][2 * np + 0], ah[mt], bf[np]);
                MMA_BF16(c[mt][2 * np + 1], ah[mt], bf[np] + 2);
            }

        if (s == 15) {
            const int ktile = gs >> 4;
            const float* csq_s = (const float*)(smem + SM_CSQ + (ktile & 1) * 1024) + wn * 64;
            float csqr[16];
#pragma unroll
            for (int nt = 0; nt < 8; nt++) {
                csqr[nt * 2 + 0] = csq_s[nt * 8 + (lane & 3) * 2 + 0];
                csqr[nt * 2 + 1] = csq_s[nt * 8 + (lane & 3) * 2 + 1];
            }
            const int kb = chunkBase + ktile * NTILE + wn * 64 + (lane & 3) * 2;
#pragma unroll
            for (int slot = 0; slot < 8; slot++) {
                const int mt = slot >> 1, h = slot & 1;
                float m = CUDART_INF_F;
#pragma unroll
                for (int nt = 0; nt < 8; nt++) {
                    m = fminf(m, fmaf(-2.f, c[mt][nt][h * 2 + 0], csqr[nt * 2 + 0]));
                    m = fminf(m, fmaf(-2.f, c[mt][nt][h * 2 + 1], csqr[nt * 2 + 1]));
                }
                if (m < b2r[slot]) {
#pragma unroll
                    for (int nt = 0; nt < 8; nt++)
#pragma unroll
                        for (int u = 0; u < 2; u++) {
                            float sc = fmaf(-2.f, c[mt][nt][h * 2 + u], csqr[nt * 2 + u]);
                            int k = kb + nt * 8 + u;
                            if (sc < b1r[slot]) {
                                b2r[slot] = b1r[slot]; i2r[slot] = i1r[slot];
                                b1r[slot] = sc;        i1r[slot] = k;
                            } else if (sc < b2r[slot]) {
                                b2r[slot] = sc; i2r[slot] = k;
                            }
                        }
                }
            }
#pragma unroll
            for (int a = 0; a < 4; a++)
#pragma unroll
                for (int b = 0; b < 8; b++)
#pragma unroll
                    for (int v = 0; v < 4; v++) c[a][b][v] = 0.f;
        }
    }

    // ---- lane-quad merge (lanes sharing a row differ in lane&3) ----
#pragma unroll
    for (int slot = 0; slot < 8; slot++) {
        float B1 = b1r[slot], B2 = b2r[slot];
        int   I1 = i1r[slot], I2 = i2r[slot];
#pragma unroll
        for (int off = 1; off <= 2; off <<= 1) {
            float C1 = __shfl_xor_sync(0xffffffffu, B1, off);
            int   J1 = __shfl_xor_sync(0xffffffffu, I1, off);
            float C2 = __shfl_xor_sync(0xffffffffu, B2, off);
            int   J2 = __shfl_xor_sync(0xffffffffu, I2, off);
            MERGE2(B1, I1, B2, I2, C1, J1, C2, J2);
        }
        b1r[slot] = B1; i1r[slot] = I1; b2r[slot] = B2; i2r[slot] = I2;
    }

    // ---- cross-warp-column merge -> top-2 per row for this chunk ----
    __syncthreads();
    float* mb1 = (float*)(smem + SM_B);
    int*   mi1 = (int*)  (smem + SM_B + 2048);
    float* mb2 = (float*)(smem + SM_B + 4096);
    int*   mi2 = (int*)  (smem + SM_B + 6144);
    if ((lane & 3) == 0) {
#pragma unroll
        for (int slot = 0; slot < 8; slot++) {
            int row = wm * 64 + (slot >> 1) * 16 + (slot & 1) * 8 + (lane >> 2);
            int idx = wn * 128 + row;
            mb1[idx] = b1r[slot]; mi1[idx] = i1r[slot];
            mb2[idx] = b2r[slot]; mi2[idx] = i2r[slot];
        }
    }
    __syncthreads();
    if (tid < 128) {
        float B1 = mb1[tid], B2 = mb2[tid];
        int   I1 = mi1[tid], I2 = mi2[tid];
#pragma unroll
        for (int w = 1; w < 4; w++) {
            float C1 = mb1[w * 128 + tid]; int J1 = mi1[w * 128 + tid];
            float C2 = mb2[w * 128 + tid]; int J2 = mi2[w * 128 + tid];
            MERGE2(B1, I1, B2, I2, C1, J1, C2, J2);
        }
        g_cand[(rowBase + tid) * 8 + chunk * 2 + 0] = I1;
        g_cand[(rowBase + tid) * 8 + chunk * 2 + 1] = I2;
    }
}

// ---------------------------------------------------------------------------
// Exact fp32 rescore of 8 candidates + gather. One warp per row.
// ---------------------------------------------------------------------------
__global__ __launch_bounds__(256) void vq_rescore(const float* __restrict__ x,
                                                  const float* __restrict__ cb,
                                                  float* __restrict__ out) {
    int row  = blockIdx.x * 8 + (threadIdx.x >> 5);
    int lane = threadIdx.x & 31;
    int kc[8];
#pragma unroll
    for (int c = 0; c < 8; c++) kc[c] = g_cand[row * 8 + c];
    const float4* xr = (const float4*)(x + (size_t)row * DIM);
    float4 xv0 = xr[lane], xv1 = xr[lane + 32];
    float d[8];
#pragma unroll
    for (int c = 0; c < 8; c++) {
        const float4* cc = (const float4*)(cb + (size_t)kc[c] * DIM);
        float4 a = cc[lane], b = cc[lane + 32];
        d[c] = xv0.x * a.x + xv0.y * a.y + xv0.z * a.z + xv0.w * a.w
             + xv1.x * b.x + xv1.y * b.y + xv1.z * b.z + xv1.w * b.w;
    }
#pragma unroll
    for (int off = 16; off; off >>= 1)
#pragma unroll
        for (int c = 0; c < 8; c++) d[c] += __shfl_xor_sync(0xffffffffu, d[c], off);
    float best = CUDART_INF_F; int bi = 0x7fffffff;
#pragma unroll
    for (int c = 0; c < 8; c++) {
        float s = fmaf(-2.f, d[c], g_csq[kc[c]]);
        if (s < best || (s == best && kc[c] < bi)) { best = s; bi = kc[c]; }
    }
    if (lane == 0) out[row] = (float)bi;
    const float4* cw = (const float4*)(cb + (size_t)bi * DIM);
    float4* oq = (float4*)(out + NROWS + (size_t)row * DIM);
    oq[lane] = cw[lane];
    oq[lane + 32] = cw[lane + 32];
}

// ---------------------------------------------------------------------------
extern "C" void kernel_launch(void* const* d_in, const int* in_sizes, int n_in,
                              void* d_out, int out_size) {
    const float* x  = (const float*)d_in[0];   // [8, 4096, 256] f32
    const float* cb = (const float*)d_in[1];   // [8192, 256] f32
    float* out = (float*)d_out;

    cudaFuncSetAttribute(vq_main, cudaFuncAttributeMaxDynamicSharedMemorySize,
                         SMEM_TOTAL);

    vq_prep<<<KCODES / 8, 256>>>(cb);
    vq_main<<<(NROWS / MT) * 4, 256, SMEM_TOTAL>>>(x);
    vq_rescore<<<NROWS / 8, 256>>>(x, cb, out);
}